// round 2
// baseline (speedup 1.0000x reference)
#include <cuda_runtime.h>
#include <cstddef>

#define BATCH 256
#define TSEQ  512
#define IDIM  64
#define HDIM  512
#define ODIM  512

typedef unsigned long long ull;

// Scratch (static device allocations are allowed; no cudaMalloc anywhere).
// g_xp: precomputed input projections, laid out [t][b][h] so each step reads a
// contiguous 512 KB slab. 256 MiB.
__device__ float g_xp[(size_t)TSEQ * BATCH * HDIM];
// Ping-pong hidden state buffers. 1 MiB total.
__device__ float g_h[2 * BATCH * HDIM];

// ---- packed f32x2 helpers (sm_100+): 2 fp32 FMAs per instruction ----
__device__ __forceinline__ ull pk2(float lo, float hi) {
    ull r; asm("mov.b64 %0, {%1,%2};" : "=l"(r) : "f"(lo), "f"(hi)); return r;
}
__device__ __forceinline__ float2 upk2(ull v) {
    float2 r; asm("mov.b64 {%0,%1}, %2;" : "=f"(r.x), "=f"(r.y) : "l"(v)); return r;
}
__device__ __forceinline__ ull fma2(ull a, ull b, ull c) {
    ull d; asm("fma.rn.f32x2 %0, %1, %2, %3;" : "=l"(d) : "l"(a), "l"(b), "l"(c)); return d;
}

// ============================================================================
// Kernel A: xp[t][b][:] = x[b][t][:] @ Whx + bh      (one CTA per (b,t) row)
// ============================================================================
__global__ void __launch_bounds__(128) xproj_kernel(
    const float* __restrict__ x, const float* __restrict__ Whx,
    const float* __restrict__ bh)
{
    __shared__ float xs[IDIM];
    int row = blockIdx.x;            // row = b*TSEQ + t
    int b = row >> 9;                // / TSEQ
    int t = row & (TSEQ - 1);
    int tid = threadIdx.x;
    if (tid < IDIM) xs[tid] = x[(size_t)row * IDIM + tid];
    __syncthreads();

    int j0 = tid * 4;                // 128 threads * 4 cols = 512
    ull a0 = 0ull, a1 = 0ull;        // bit pattern 0 == {0.0f, 0.0f}
    #pragma unroll 8
    for (int k = 0; k < IDIM; k++) {
        float4 w = *reinterpret_cast<const float4*>(Whx + (size_t)k * HDIM + j0);
        ull xv = pk2(xs[k], xs[k]);
        a0 = fma2(pk2(w.x, w.y), xv, a0);
        a1 = fma2(pk2(w.z, w.w), xv, a1);
    }
    float4 bv = *reinterpret_cast<const float4*>(bh + j0);
    float2 p0 = upk2(a0), p1 = upk2(a1);
    float4 o;
    o.x = p0.x + bv.x; o.y = p0.y + bv.y;
    o.z = p1.x + bv.z; o.w = p1.y + bv.w;
    *reinterpret_cast<float4*>(g_xp + ((size_t)t * BATCH + b) * HDIM + j0) = o;
}

// ============================================================================
// Kernel B: one recurrence step. h_out = tanh(xp_t + h_in @ Whh)
// Grid: (HDIM/64, BATCH/16) = (8,16) = 128 CTAs, 128 threads.
// CTA tile: 16 batch rows x 64 output cols, K = 512.
// h tile staged in SMEM, transposed with pad-2 stride (18 floats) so the
// mainloop does broadcast LDS.64 of two adjacent batch rows.
// Per k per thread: 1 LDG.128 (Whh), 1 LDS.64 (h pair), 4 FFMA2 -> 8 MACs.
// ============================================================================
__global__ void __launch_bounds__(128, 1) rnn_step_kernel(
    const float* __restrict__ xp_t, const float* __restrict__ Whh,
    const float* __restrict__ h_in, float* __restrict__ h_out, int first)
{
    __shared__ float hs[HDIM * 18];  // [k][b] transposed, stride 18 (36864 B)

    int tid = threadIdx.x;
    int jt = tid & 15;               // 16 j-groups of 4 cols
    int bq = tid >> 4;               // 8 b-groups of 2 rows
    int b0 = blockIdx.y * 16;
    int jg = blockIdx.x * 64 + jt * 4;

    ull a00 = 0ull, a01 = 0ull, a10 = 0ull, a11 = 0ull;  // [jpair][bsub]

    if (!first) {
        // Coalesced global read (k fast), transposed SMEM write.
        for (int idx = tid; idx < 16 * HDIM; idx += 128) {
            int bb = idx >> 9;
            int k  = idx & (HDIM - 1);
            hs[k * 18 + bb] = h_in[(size_t)(b0 + bb) * HDIM + k];
        }
        __syncthreads();

        const float* wp = Whh + jg;
        int hoff = bq * 2;
        #pragma unroll 8
        for (int k = 0; k < HDIM; k++) {
            float4 w  = *reinterpret_cast<const float4*>(wp + (size_t)k * HDIM);
            float2 h2 = *reinterpret_cast<const float2*>(hs + k * 18 + hoff);
            ull w01 = pk2(w.x, w.y);
            ull w23 = pk2(w.z, w.w);
            ull hb0 = pk2(h2.x, h2.x);
            ull hb1 = pk2(h2.y, h2.y);
            a00 = fma2(w01, hb0, a00);
            a10 = fma2(w23, hb0, a10);
            a01 = fma2(w01, hb1, a01);
            a11 = fma2(w23, hb1, a11);
        }
    }

    // Epilogue: add xp, tanh (accurate), store.
    #pragma unroll
    for (int s = 0; s < 2; s++) {
        int gb = b0 + bq * 2 + s;
        float4 xv = *reinterpret_cast<const float4*>(xp_t + (size_t)gb * HDIM + jg);
        float2 p0 = upk2(s ? a01 : a00);
        float2 p1 = upk2(s ? a11 : a10);
        float4 o;
        o.x = tanhf(xv.x + p0.x);
        o.y = tanhf(xv.y + p0.y);
        o.z = tanhf(xv.z + p1.x);
        o.w = tanhf(xv.w + p1.y);
        *reinterpret_cast<float4*>(h_out + (size_t)gb * HDIM + jg) = o;
    }
}

// ============================================================================
// Kernel C: out[b][:] = softmax(h[b][:] @ Wph + bo). One CTA per batch row.
// ============================================================================
__global__ void __launch_bounds__(128) out_softmax_kernel(
    const float* __restrict__ h, const float* __restrict__ Wph,
    const float* __restrict__ bo, float* __restrict__ out)
{
    __shared__ float hsr[HDIM];
    __shared__ float red[128];
    int b = blockIdx.x, tid = threadIdx.x;
    for (int k = tid; k < HDIM; k += 128) hsr[k] = h[(size_t)b * HDIM + k];
    __syncthreads();

    int j0 = tid * 4;
    ull a0 = 0ull, a1 = 0ull;
    #pragma unroll 8
    for (int k = 0; k < HDIM; k++) {
        float4 w = *reinterpret_cast<const float4*>(Wph + (size_t)k * ODIM + j0);
        ull hv = pk2(hsr[k], hsr[k]);
        a0 = fma2(pk2(w.x, w.y), hv, a0);
        a1 = fma2(pk2(w.z, w.w), hv, a1);
    }
    float4 bv = *reinterpret_cast<const float4*>(bo + j0);
    float2 p0 = upk2(a0), p1 = upk2(a1);
    float4 v;
    v.x = p0.x + bv.x; v.y = p0.y + bv.y;
    v.z = p1.x + bv.z; v.w = p1.y + bv.w;

    // row max
    float m = fmaxf(fmaxf(v.x, v.y), fmaxf(v.z, v.w));
    red[tid] = m;
    __syncthreads();
    for (int s = 64; s > 0; s >>= 1) {
        if (tid < s) red[tid] = fmaxf(red[tid], red[tid + s]);
        __syncthreads();
    }
    m = red[0];
    __syncthreads();

    // exp + row sum
    v.x = expf(v.x - m); v.y = expf(v.y - m);
    v.z = expf(v.z - m); v.w = expf(v.w - m);
    red[tid] = v.x + v.y + v.z + v.w;
    __syncthreads();
    for (int s = 64; s > 0; s >>= 1) {
        if (tid < s) red[tid] += red[tid + s];
        __syncthreads();
    }
    float inv = 1.0f / red[0];

    v.x *= inv; v.y *= inv; v.z *= inv; v.w *= inv;
    *reinterpret_cast<float4*>(out + (size_t)b * ODIM + j0) = v;
}

// ============================================================================
// Launch: 1 projection kernel + 512 step kernels + 1 softmax kernel, all on
// the default stream (graph-capturable, allocation-free, deterministic).
// ============================================================================
extern "C" void kernel_launch(void* const* d_in, const int* in_sizes, int n_in,
                              void* d_out, int out_size)
{
    const float* x   = (const float*)d_in[0];
    const float* Whx = (const float*)d_in[1];
    const float* Whh = (const float*)d_in[2];
    const float* bh  = (const float*)d_in[3];
    const float* Wph = (const float*)d_in[4];
    const float* bo  = (const float*)d_in[5];
    float* out = (float*)d_out;

    float* xp;    cudaGetSymbolAddress((void**)&xp, g_xp);
    float* hbase; cudaGetSymbolAddress((void**)&hbase, g_h);
    float* hb0 = hbase;
    float* hb1 = hbase + (size_t)BATCH * HDIM;

    xproj_kernel<<<BATCH * TSEQ, 128>>>(x, Whx, bh);

    for (int t = 0; t < TSEQ; t++) {
        float* hin  = (t & 1) ? hb1 : hb0;
        float* hout = (t & 1) ? hb0 : hb1;
        rnn_step_kernel<<<dim3(HDIM / 64, BATCH / 16), 128>>>(
            xp + (size_t)t * BATCH * HDIM, Whh, hin, hout, t == 0);
    }

    // After t = 511, last write went to hb0 (t even -> hout = hb1; t=511 odd -> hb0).
    out_softmax_kernel<<<BATCH, 128>>>(hb0, Wph, bo, out);
}

// round 3
// speedup vs baseline: 2.1178x; 2.1178x over previous
#include <cuda_runtime.h>
#include <cstdint>
#include <cstddef>

#define BATCH 256
#define TSEQ  512
#define IDIM  64
#define HDIM  512
#define ODIM  512
#define GRID_STEP 128        // persistent CTAs (<= 148 SMs, 1 CTA/SM -> all co-resident)
#define STEP_THREADS 128

typedef unsigned long long ull;

// ---- scratch (static device allocations only; no cudaMalloc anywhere) ----
__device__ float  g_xp[(size_t)TSEQ * BATCH * HDIM];   // [t][b][h], 256 MiB
// hidden state, transposed + splatted: g_ht[buf][h*BATCH + b] = {v, v}
__device__ float2 g_ht[2][(size_t)HDIM * BATCH];       // 2 MiB
__device__ unsigned g_bar;                             // grid barrier counter (self-resetting)

// ---- packed f32x2 helpers ----
__device__ __forceinline__ ull pk2(float lo, float hi) {
    ull r; asm("mov.b64 %0, {%1,%2};" : "=l"(r) : "f"(lo), "f"(hi)); return r;
}
__device__ __forceinline__ float2 upk2(ull v) {
    float2 r; asm("mov.b64 {%0,%1}, %2;" : "=f"(r.x), "=f"(r.y) : "l"(v)); return r;
}
__device__ __forceinline__ ull fma2(ull a, ull b, ull c) {
    ull d; asm("fma.rn.f32x2 %0, %1, %2, %3;" : "=l"(d) : "l"(a), "l"(b), "l"(c)); return d;
}

// ---- grid barrier ----
__device__ __forceinline__ void bar_wait(unsigned target) {
    if (threadIdx.x == 0) {
        unsigned v;
        do {
            asm volatile("ld.acquire.gpu.global.u32 %0, [%1];"
                         : "=r"(v) : "l"(&g_bar) : "memory");
        } while (v < target);
    }
    __syncthreads();
}
__device__ __forceinline__ void bar_arrive(unsigned total) {
    __syncthreads();                       // all CTA threads' h stores done
    if (threadIdx.x == 0) {
        unsigned old;
        asm volatile("atom.release.gpu.global.add.u32 %0, [%1], %2;"
                     : "=r"(old) : "l"(&g_bar), "r"(1u) : "memory");
        if (old == total - 1u)             // very last arrival of the launch: reset
            asm volatile("st.relaxed.gpu.global.u32 [%0], %1;"
                         :: "l"(&g_bar), "r"(0u) : "memory");
    }
}

// ============================================================================
// Kernel A: xp[t][b][:] = x[b][t][:] @ Whx + bh.  4 rows (same b) per CTA to
// amortize Whx LDG over 8 FFMA2.
// ============================================================================
__global__ void __launch_bounds__(128) xproj_kernel(
    const float* __restrict__ x, const float* __restrict__ Whx,
    const float* __restrict__ bh)
{
    __shared__ float xs[4][IDIM];
    int row0 = blockIdx.x * 4;       // row = b*TSEQ + t; 4 consecutive t, same b
    int b = row0 >> 9, t0 = row0 & (TSEQ - 1);
    int tid = threadIdx.x;
    for (int i = tid; i < 4 * IDIM; i += 128)
        xs[i >> 6][i & 63] = x[(size_t)(row0 + (i >> 6)) * IDIM + (i & 63)];
    __syncthreads();

    int j0 = tid * 4;
    ull a[4][2] = {};
    #pragma unroll 4
    for (int k = 0; k < IDIM; k++) {
        float4 w = *reinterpret_cast<const float4*>(Whx + (size_t)k * HDIM + j0);
        ull w01 = pk2(w.x, w.y), w23 = pk2(w.z, w.w);
        #pragma unroll
        for (int r = 0; r < 4; r++) {
            float xv = xs[r][k];
            ull x2 = pk2(xv, xv);
            a[r][0] = fma2(w01, x2, a[r][0]);
            a[r][1] = fma2(w23, x2, a[r][1]);
        }
    }
    float4 bv = *reinterpret_cast<const float4*>(bh + j0);
    #pragma unroll
    for (int r = 0; r < 4; r++) {
        float2 p0 = upk2(a[r][0]), p1 = upk2(a[r][1]);
        float4 o;
        o.x = p0.x + bv.x; o.y = p0.y + bv.y;
        o.z = p1.x + bv.z; o.w = p1.y + bv.w;
        *reinterpret_cast<float4*>(
            g_xp + ((size_t)(t0 + r) * BATCH + b) * HDIM + j0) = o;
    }
}

// ============================================================================
// Kernel B: persistent recurrence. 128 CTAs x 128 threads, grid (16 j, 8 b).
// CTA tile 32j x 32b; thread tile 4j x 2b. Whh slice (64KB) SMEM-resident.
// h staged per step via double-buffered cp.async.cg (L1-bypass), k-chunks of 128.
// ============================================================================
__global__ void __launch_bounds__(STEP_THREADS, 1) rnn_persistent(
    const float* __restrict__ Whh)
{
    extern __shared__ char smraw[];
    float* ws = reinterpret_cast<float*>(smraw);          // [512][32]  64 KB
    char*  hsb = smraw + 65536;                           // 2 x [128][32] float2, 32 KB each

    const int tid  = threadIdx.x;
    const int lane = tid & 31, wrp = tid >> 5;
    const int jg = lane & 7, bg = lane >> 3;
    const int j0c = blockIdx.x * 32;
    const int b0c = blockIdx.y * 32;
    const int j0 = j0c + jg * 4;
    const int bl = wrp * 8 + bg * 2;        // local b (even)
    const int b0 = b0c + bl;

    // ---- load Whh slice into SMEM (once) ----
    for (int i = tid; i < 512 * 8; i += STEP_THREADS) {
        int k = i >> 3, c = i & 7;
        *reinterpret_cast<float4*>(ws + k * 32 + c * 4) =
            *reinterpret_cast<const float4*>(Whh + (size_t)k * HDIM + j0c + c * 4);
    }
    __syncthreads();

    // staging thread mapping: 16 segments of 16B per k-row; 8 k-rows per pass
    const int seg  = tid & 15;
    const int krow = tid >> 4;              // 0..7

    for (int t = 0; t < TSEQ; t++) {
        const float* xpt = g_xp + (size_t)t * BATCH * HDIM;
        // prefetch xp early (independent of barrier)
        float4 xv0 = *reinterpret_cast<const float4*>(xpt + (size_t)b0 * HDIM + j0);
        float4 xv1 = *reinterpret_cast<const float4*>(xpt + (size_t)(b0 + 1) * HDIM + j0);
        ull a0 = 0ull, a1 = 0ull, a2 = 0ull, a3 = 0ull;

        if (t > 0) {
            bar_wait((unsigned)t * GRID_STEP);
            const float2* hin = g_ht[(t - 1) & 1];

            // issue chunk 0
            {
                const float2* src = hin + (size_t)krow * BATCH + b0c + seg * 2;
                uint32_t dst = (uint32_t)__cvta_generic_to_shared(
                    hsb + ((size_t)krow * 32 + seg * 2) * 8);
                #pragma unroll
                for (int p = 0; p < 16; p++)
                    asm volatile("cp.async.cg.shared.global [%0], [%1], 16;"
                                 :: "r"(dst + p * 2048), "l"(src + p * 2048) : "memory");
                asm volatile("cp.async.commit_group;" ::: "memory");
            }

            #pragma unroll
            for (int c = 0; c < 4; c++) {
                asm volatile("cp.async.wait_group 0;" ::: "memory");
                __syncthreads();   // chunk c visible to all; prev compute done by all
                if (c < 3) {
                    const float2* src = hin + (size_t)((c + 1) * 128 + krow) * BATCH
                                        + b0c + seg * 2;
                    uint32_t dst = (uint32_t)__cvta_generic_to_shared(
                        hsb + ((size_t)((c + 1) & 1)) * 32768
                            + ((size_t)krow * 32 + seg * 2) * 8);
                    #pragma unroll
                    for (int p = 0; p < 16; p++)
                        asm volatile("cp.async.cg.shared.global [%0], [%1], 16;"
                                     :: "r"(dst + p * 2048), "l"(src + p * 2048) : "memory");
                    asm volatile("cp.async.commit_group;" ::: "memory");
                }
                // compute chunk c from buffer c&1
                const float* wk = ws + (c * 128) * 32 + jg * 4;
                const char*  hk = hsb + (c & 1) * 32768 + bl * 8;
                #pragma unroll 8
                for (int kl = 0; kl < 128; kl++) {
                    float4 w4 = *reinterpret_cast<const float4*>(wk + (size_t)kl * 32);
                    float4 h4 = *reinterpret_cast<const float4*>(hk + (size_t)kl * 256);
                    ull w01 = pk2(w4.x, w4.y), w23 = pk2(w4.z, w4.w);
                    ull hlo = pk2(h4.x, h4.y), hhi = pk2(h4.z, h4.w);  // {h0,h0},{h1,h1}
                    a0 = fma2(w01, hlo, a0);
                    a1 = fma2(w23, hlo, a1);
                    a2 = fma2(w01, hhi, a2);
                    a3 = fma2(w23, hhi, a3);
                }
            }
        }

        // ---- epilogue: add xp, tanh, store splatted-transposed h ----
        float2* hout = g_ht[t & 1];
        float2 p0 = upk2(a0), p1 = upk2(a1), p2 = upk2(a2), p3 = upk2(a3);
        float o0[4] = { tanhf(xv0.x + p0.x), tanhf(xv0.y + p0.y),
                        tanhf(xv0.z + p1.x), tanhf(xv0.w + p1.y) };
        float o1[4] = { tanhf(xv1.x + p2.x), tanhf(xv1.y + p2.y),
                        tanhf(xv1.z + p3.x), tanhf(xv1.w + p3.y) };
        #pragma unroll
        for (int jj = 0; jj < 4; jj++) {
            hout[(size_t)(j0 + jj) * BATCH + b0]     = make_float2(o0[jj], o0[jj]);
            hout[(size_t)(j0 + jj) * BATCH + b0 + 1] = make_float2(o1[jj], o1[jj]);
        }
        bar_arrive((unsigned)TSEQ * GRID_STEP);
    }
}

// ============================================================================
// Kernel C: out[b][:] = softmax(h_last[b][:] @ Wph + bo). h_last is g_ht[1]
// (t=511 writes buffer 511&1 = 1), transposed+splatted: read .x at [k*BATCH+b].
// ============================================================================
__global__ void __launch_bounds__(128) out_softmax_kernel(
    const float* __restrict__ Wph, const float* __restrict__ bo,
    float* __restrict__ out)
{
    __shared__ float hsr[HDIM];
    __shared__ float red[128];
    int b = blockIdx.x, tid = threadIdx.x;
    for (int k = tid; k < HDIM; k += 128)
        hsr[k] = g_ht[1][(size_t)k * BATCH + b].x;
    __syncthreads();

    int j0 = tid * 4;
    ull a0 = 0ull, a1 = 0ull;
    #pragma unroll 8
    for (int k = 0; k < HDIM; k++) {
        float4 w = *reinterpret_cast<const float4*>(Wph + (size_t)k * ODIM + j0);
        ull hv = pk2(hsr[k], hsr[k]);
        a0 = fma2(pk2(w.x, w.y), hv, a0);
        a1 = fma2(pk2(w.z, w.w), hv, a1);
    }
    float4 bv = *reinterpret_cast<const float4*>(bo + j0);
    float2 p0 = upk2(a0), p1 = upk2(a1);
    float4 v;
    v.x = p0.x + bv.x; v.y = p0.y + bv.y;
    v.z = p1.x + bv.z; v.w = p1.y + bv.w;

    float m = fmaxf(fmaxf(v.x, v.y), fmaxf(v.z, v.w));
    red[tid] = m;
    __syncthreads();
    for (int s = 64; s > 0; s >>= 1) {
        if (tid < s) red[tid] = fmaxf(red[tid], red[tid + s]);
        __syncthreads();
    }
    m = red[0];
    __syncthreads();

    v.x = expf(v.x - m); v.y = expf(v.y - m);
    v.z = expf(v.z - m); v.w = expf(v.w - m);
    red[tid] = v.x + v.y + v.z + v.w;
    __syncthreads();
    for (int s = 64; s > 0; s >>= 1) {
        if (tid < s) red[tid] += red[tid + s];
        __syncthreads();
    }
    float inv = 1.0f / red[0];
    v.x *= inv; v.y *= inv; v.z *= inv; v.w *= inv;
    *reinterpret_cast<float4*>(out + (size_t)b * ODIM + j0) = v;
}

// ============================================================================
extern "C" void kernel_launch(void* const* d_in, const int* in_sizes, int n_in,
                              void* d_out, int out_size)
{
    const float* x   = (const float*)d_in[0];
    const float* Whx = (const float*)d_in[1];
    const float* Whh = (const float*)d_in[2];
    const float* bh  = (const float*)d_in[3];
    const float* Wph = (const float*)d_in[4];
    const float* bo  = (const float*)d_in[5];
    float* out = (float*)d_out;

    cudaFuncSetAttribute(rnn_persistent,
                         cudaFuncAttributeMaxDynamicSharedMemorySize, 131072);

    xproj_kernel<<<BATCH * TSEQ / 4, 128>>>(x, Whx, bh);
    rnn_persistent<<<dim3(16, 8), STEP_THREADS, 131072>>>(Whh);
    out_softmax_kernel<<<BATCH, 128>>>(Wph, bo, out);
}